// round 16
// baseline (speedup 1.0000x reference)
#include <cuda_runtime.h>
#include <cstdint>

// LGA: out[n,c,h,w] = sum_{i,j in 5x5} in1[n,c,h+i-2,w+j-2] * in2[n,i*5+j,h,w]
// Shapes fixed: in1 [4,32,384,768] f32, in2 [4,25,384,768] f32.
//
// Round-16 = round-14 (staggered grid, conflict-free two-LDS.128 windows,
// 4-stage cp.async ring of channel pairs) with:
//  - TILE_H 8 -> 12 (BY=12, 192 threads): vertical halo amplification drops
//    1.5x -> 1.33x (-11% smem-write wavefronts and L2 in1 fill traffic),
//    fewer blocks (1664 vs 2496) -> fewer one-time weight prologues.
//  - prologue reorder: cp.async copies for the first 3 pairs are issued
//    BEFORE the 50 weight LDGs, so weight-load latency overlaps the DMA.

#define NDIM 4
#define CDIM 32
#define HDIM 384
#define WDIM 768
#define KTAPS 25
#define PLANE (HDIM * WDIM)

#define BX 16
#define BY 12
#define NTHR (BX * BY)                // 192
#define TILE_H 12
#define SROWS (TILE_H + 4)            // 16
#define SPITCH 72                     // floats per smem row (288 B)
#define STAGE_ELEMS (SROWS * SPITCH)  // 1152
#define STAGES 4                      // ring of channel PAIRS
#define NPAIR (CDIM / 2)              // 16
#define CHUNKS_PER_ROW 18             // 18 x 16B = 72 floats
#define NCHUNK (SROWS * CHUNKS_PER_ROW)  // 288
#define GRIDX 13                      // staggered quads cover [-2, 770)

typedef unsigned long long u64;

__device__ __forceinline__ uint32_t smem_u32(const void* p) {
    return (uint32_t)__cvta_generic_to_shared(p);
}
__device__ __forceinline__ void cp_async16(uint32_t dst, const float* src, int sz) {
    asm volatile("cp.async.cg.shared.global [%0], [%1], 16, %2;\n"
                 :: "r"(dst), "l"(src), "r"(sz));
}
__device__ __forceinline__ void cp_commit() {
    asm volatile("cp.async.commit_group;\n" ::: "memory");
}
__device__ __forceinline__ void cp_wait2() {
    asm volatile("cp.async.wait_group 2;\n" ::: "memory");
}
__device__ __forceinline__ u64 pack2(float lo, float hi) {
    u64 r;
    asm("mov.b64 %0, {%1, %2};" : "=l"(r) : "f"(lo), "f"(hi));
    return r;
}
__device__ __forceinline__ void unpack2(u64 v, float& lo, float& hi) {
    asm("mov.b64 {%0, %1}, %2;" : "=f"(lo), "=f"(hi) : "l"(v));
}
__device__ __forceinline__ void fma2(u64& acc, u64 a, u64 b) {
    asm("fma.rn.f32x2 %0, %1, %2, %0;" : "+l"(acc) : "l"(a), "l"(b));
}

__global__ __launch_bounds__(NTHR, 2)
void lga_kernel(const float* __restrict__ in1,
                const float* __restrict__ in2,
                float* __restrict__ out) {
    __shared__ __align__(16) float ring[STAGES][2][STAGE_ELEMS];  // 36.9 KB

    const int tx = threadIdx.x;            // 0..15
    const int ty = threadIdx.y;            // 0..11
    const int tid = ty * BX + tx;
    const int hbase = blockIdx.y * TILE_H;
    const int n = blockIdx.z;

    const int h  = hbase + ty;                       // output row
    const int w0 = 64 * blockIdx.x + 4 * tx - 2;     // first of 4 output cols
    const int G0 = 64 * blockIdx.x - 8;              // staged tile col0 (16B al)

    const bool fullq = (w0 >= 0) && (w0 <= WDIM - 4);
    const bool loEdge = (w0 == -2);                  // cols 0,1 valid (.z,.w)
    const bool hiEdge = (w0 == WDIM - 2);            // cols 766,767 (.x,.y)

    // ---- copy roles: up to 2 16B chunks per thread per channel ----
    const float* in1n = in1 + (size_t)n * CDIM * PLANE;
    int  goff0 = 0, goff1 = 0, cpsz0 = 0, cpsz1 = 0, soff0 = 0, soff1 = 0;
    bool act1 = false;
    {
        int k = tid;                                  // chunk 0 (always active)
        int r = k / CHUNKS_PER_ROW, ch = k - r * CHUNKS_PER_ROW;
        int gy = hbase - 2 + r, gx0 = G0 + 4 * ch;
        bool v = (gy >= 0) && (gy < HDIM) && (gx0 >= 0) && (gx0 + 3 < WDIM);
        goff0 = v ? (gy * WDIM + gx0) : 0;
        cpsz0 = v ? 16 : 0;
        soff0 = r * SPITCH + 4 * ch;

        k = tid + NTHR;                               // chunk 1
        act1 = (k < NCHUNK);
        r = k / CHUNKS_PER_ROW; ch = k - r * CHUNKS_PER_ROW;
        gy = hbase - 2 + r; gx0 = G0 + 4 * ch;
        v = act1 && (gy >= 0) && (gy < HDIM) && (gx0 >= 0) && (gx0 + 3 < WDIM);
        goff1 = v ? (gy * WDIM + gx0) : 0;
        cpsz1 = v ? 16 : 0;
        soff1 = r * SPITCH + 4 * ch;
    }

    auto issue = [&](int p, int s) {
        const float* srcA = in1n + (size_t)(2 * p) * PLANE;
        const float* srcB = srcA + PLANE;
        uint32_t dA = smem_u32(&ring[s][0][0]);
        uint32_t dB = smem_u32(&ring[s][1][0]);
        cp_async16(dA + 4 * soff0, srcA + goff0, cpsz0);
        cp_async16(dB + 4 * soff0, srcB + goff0, cpsz0);
        if (act1) {
            cp_async16(dA + 4 * soff1, srcA + goff1, cpsz1);
            cp_async16(dB + 4 * soff1, srcB + goff1, cpsz1);
        }
        cp_commit();
    };

    // ---- kick off the DMA pipeline FIRST (overlaps the weight prologue) ----
    issue(0, 0);
    issue(1, 1);
    issue(2, 2);

    // ---- 25 per-pixel weight quads -> 50 packed f32x2 registers ----
    // global side is only 8B-aligned (w0 == 2 mod 4) -> float2 loads
    u64 w01[KTAPS], w23[KTAPS];
    {
        const float* wrow = in2 + ((size_t)n * KTAPS * HDIM + h) * WDIM;
#pragma unroll
        for (int t = 0; t < KTAPS; t++) {
            const float* wp = wrow + (size_t)t * PLANE;
            if (fullq) {
                float2 a = __ldcs((const float2*)(wp + w0));
                float2 b = __ldcs((const float2*)(wp + w0 + 2));
                w01[t] = pack2(a.x, a.y);
                w23[t] = pack2(b.x, b.y);
            } else if (loEdge) {
                float2 b = __ldcs((const float2*)(wp + 0));
                w01[t] = 0;
                w23[t] = pack2(b.x, b.y);
            } else if (hiEdge) {
                float2 a = __ldcs((const float2*)(wp + (WDIM - 2)));
                w01[t] = pack2(a.x, a.y);
                w23[t] = 0;
            } else {
                w01[t] = 0;
                w23[t] = 0;
            }
        }
    }

    float* pon = out + (size_t)n * CDIM * PLANE + (size_t)h * WDIM;

#pragma unroll 1
    for (int p = 0; p < NPAIR; p++) {
        const int s = p & (STAGES - 1);

        cp_wait2();          // pair p complete (>=2 pairs still flying)
        __syncthreads();     // visibility + ring-reuse fence

        if (p + 3 < NPAIR) issue(p + 3, (p + 3) & (STAGES - 1));
        else               cp_commit();   // keep wait-count math fixed

#pragma unroll
        for (int half = 0; half < 2; half++) {
            // window (w0-2 .. w0+5) = staged offsets 4tx+4 .. 4tx+11:
            // exactly two aligned LDS.128 per tap row, conflict-free.
            const float* basep = &ring[s][half][ty * SPITCH + 4 * tx + 4];
            u64 acc01 = 0, acc23 = 0;
#pragma unroll
            for (int i = 0; i < 5; i++) {
                const float* rp = basep + i * SPITCH;
                float4 Q1 = *(const float4*)(rp);       // d0..d3
                float4 Q2 = *(const float4*)(rp + 4);   // d4..d7

                u64 p01 = pack2(Q1.x, Q1.y);
                u64 p12 = pack2(Q1.y, Q1.z);
                u64 p23 = pack2(Q1.z, Q1.w);
                u64 p34 = pack2(Q1.w, Q2.x);
                u64 p45 = pack2(Q2.x, Q2.y);
                u64 p56 = pack2(Q2.y, Q2.z);
                u64 p67 = pack2(Q2.z, Q2.w);

                const u64* wr01 = &w01[5 * i];
                const u64* wr23 = &w23[5 * i];
                fma2(acc01, p01, wr01[0]);
                fma2(acc23, p23, wr23[0]);
                fma2(acc01, p12, wr01[1]);
                fma2(acc23, p34, wr23[1]);
                fma2(acc01, p23, wr01[2]);
                fma2(acc23, p45, wr23[2]);
                fma2(acc01, p34, wr01[3]);
                fma2(acc23, p56, wr23[3]);
                fma2(acc01, p45, wr01[4]);
                fma2(acc23, p67, wr23[4]);
            }
            float o0, o1, o2, o3;
            unpack2(acc01, o0, o1);
            unpack2(acc23, o2, o3);
            float* pc = pon + (size_t)(2 * p + half) * PLANE;
            if (fullq) {
                __stcs((float2*)(pc + w0),     make_float2(o0, o1));
                __stcs((float2*)(pc + w0 + 2), make_float2(o2, o3));
            } else if (loEdge) {
                __stcs((float2*)(pc + 0), make_float2(o2, o3));
            } else if (hiEdge) {
                __stcs((float2*)(pc + (WDIM - 2)), make_float2(o0, o1));
            }
        }
    }
}

extern "C" void kernel_launch(void* const* d_in, const int* in_sizes, int n_in,
                              void* d_out, int out_size) {
    const float* in1 = (const float*)d_in[0];
    const float* in2 = (const float*)d_in[1];
    float* out = (float*)d_out;

    dim3 block(BX, BY);
    dim3 grid(GRIDX, HDIM / TILE_H, NDIM);  // 13 x 32 x 4
    lga_kernel<<<grid, block>>>(in1, in2, out);
}

// round 17
// speedup vs baseline: 1.1359x; 1.1359x over previous
#include <cuda_runtime.h>
#include <cuda.h>
#include <cstdint>

// LGA: out[n,c,h,w] = sum_{i,j in 5x5} in1[n,c,h+i-2,w+j-2] * in2[n,i*5+j,h,w]
// Shapes fixed: in1 [4,32,384,768] f32, in2 [4,25,384,768] f32.
//
// Round-17 = round-14 (staggered grid, conflict-free two-LDS.128 windows,
// 4-stage ring of channel pairs, 100 taps in registers, fma.rn.f32x2) with
// the cp.async staging replaced by TMA (cp.async.bulk.tensor.3d):
//  - one thread issues 2 box loads [72 x 12] per channel pair against an
//    mbarrier; smem writes ride the dedicated async path instead of LSU
//    wavefronts (the LDGSTS smem-write slots vanish from the L1 pipe).
//  - TMA zero-fills out-of-bounds coords -> border handling in the copy
//    path disappears entirely.
//  - tensormap built host-side per launch via the driver entry point
//    (no -lcuda needed), passed by value as __grid_constant__.

#define NDIM 4
#define CDIM 32
#define HDIM 384
#define WDIM 768
#define KTAPS 25
#define PLANE (HDIM * WDIM)

#define BX 16
#define BY 8
#define NTHR (BX * BY)                // 128
#define TILE_H 8
#define SROWS (TILE_H + 4)            // 12
#define SPITCH 72                     // floats per smem row (288 B)
#define STAGE_ELEMS (SROWS * SPITCH)  // 864 floats = 3456 B (27*128)
#define STAGES 4                      // ring of channel PAIRS
#define NPAIR (CDIM / 2)              // 16
#define GRIDX 13                      // staggered quads cover [-2, 770)
#define PAIR_BYTES (2 * STAGE_ELEMS * 4)  // 6912

typedef unsigned long long u64;

__device__ __forceinline__ uint32_t smem_u32(const void* p) {
    return (uint32_t)__cvta_generic_to_shared(p);
}
__device__ __forceinline__ u64 pack2(float lo, float hi) {
    u64 r;
    asm("mov.b64 %0, {%1, %2};" : "=l"(r) : "f"(lo), "f"(hi));
    return r;
}
__device__ __forceinline__ void unpack2(u64 v, float& lo, float& hi) {
    asm("mov.b64 {%0, %1}, %2;" : "=f"(lo), "=f"(hi) : "l"(v));
}
__device__ __forceinline__ void fma2(u64& acc, u64 a, u64 b) {
    asm("fma.rn.f32x2 %0, %1, %2, %0;" : "+l"(acc) : "l"(a), "l"(b));
}
__device__ __forceinline__ void mbar_init(uint32_t mb, uint32_t count) {
    asm volatile("mbarrier.init.shared.b64 [%0], %1;" :: "r"(mb), "r"(count)
                 : "memory");
}
__device__ __forceinline__ void mbar_expect_tx(uint32_t mb, uint32_t bytes) {
    asm volatile("mbarrier.arrive.expect_tx.shared.b64 _, [%0], %1;"
                 :: "r"(mb), "r"(bytes) : "memory");
}
__device__ __forceinline__ void mbar_wait(uint32_t mb, uint32_t parity) {
    asm volatile(
        "{\n\t.reg .pred P;\n"
        "W%=:\n\t"
        "mbarrier.try_wait.parity.acquire.cta.shared::cta.b64 P, [%0], %1;\n\t"
        "@!P bra W%=;\n\t}"
        :: "r"(mb), "r"(parity) : "memory");
}
__device__ __forceinline__ void tma_load_3d(uint32_t dst, const void* tmap,
                                            int cx, int cy, int cz,
                                            uint32_t mb) {
    asm volatile(
        "cp.async.bulk.tensor.3d.shared::cta.global.tile"
        ".mbarrier::complete_tx::bytes [%0], [%1, {%2, %3, %4}], [%5];"
        :: "r"(dst), "l"(tmap), "r"(cx), "r"(cy), "r"(cz), "r"(mb)
        : "memory");
}

__global__ __launch_bounds__(NTHR, 3)
void lga_kernel(const __grid_constant__ CUtensorMap tma_in1,
                const float* __restrict__ in2,
                float* __restrict__ out) {
    __shared__ __align__(128) float ring[STAGES][2][STAGE_ELEMS];  // 27.6 KB
    __shared__ __align__(8) u64 mbar[STAGES];

    const int tx = threadIdx.x;            // 0..15
    const int ty = threadIdx.y;            // 0..7
    const int tid = ty * BX + tx;
    const int hbase = blockIdx.y * TILE_H;
    const int n = blockIdx.z;

    const int h  = hbase + ty;                       // output row
    const int w0 = 64 * blockIdx.x + 4 * tx - 2;     // first of 4 output cols
    const int G0 = 64 * blockIdx.x - 8;              // staged tile col0
    const int hy0 = hbase - 2;                       // staged tile row0
    const int zbase = n * CDIM;                      // plane index of channel 0

    const bool fullq = (w0 >= 0) && (w0 <= WDIM - 4);
    const bool loEdge = (w0 == -2);                  // cols 0,1 valid (.z,.w)
    const bool hiEdge = (w0 == WDIM - 2);            // cols 766,767 (.x,.y)

    // ---- mbarrier init, then kick off the first 3 pair loads (tid 0) ----
    if (tid == 0) {
#pragma unroll
        for (int s = 0; s < STAGES; s++)
            mbar_init(smem_u32(&mbar[s]), 1);
    }
    __syncthreads();

    auto issue = [&](int p) {
        const int s = p & (STAGES - 1);
        uint32_t mb = smem_u32(&mbar[s]);
        mbar_expect_tx(mb, PAIR_BYTES);
        tma_load_3d(smem_u32(&ring[s][0][0]), &tma_in1, G0, hy0,
                    zbase + 2 * p, mb);
        tma_load_3d(smem_u32(&ring[s][1][0]), &tma_in1, G0, hy0,
                    zbase + 2 * p + 1, mb);
    };
    if (tid == 0) {
        issue(0);
        issue(1);
        issue(2);
    }

    // ---- 25 per-pixel weight quads -> 50 packed f32x2 registers ----
    // (overlaps the in-flight TMA loads; w0 == 2 mod 4 -> float2 loads)
    u64 w01[KTAPS], w23[KTAPS];
    {
        const float* wrow = in2 + ((size_t)n * KTAPS * HDIM + h) * WDIM;
#pragma unroll
        for (int t = 0; t < KTAPS; t++) {
            const float* wp = wrow + (size_t)t * PLANE;
            if (fullq) {
                float2 a = __ldcs((const float2*)(wp + w0));
                float2 b = __ldcs((const float2*)(wp + w0 + 2));
                w01[t] = pack2(a.x, a.y);
                w23[t] = pack2(b.x, b.y);
            } else if (loEdge) {
                float2 b = __ldcs((const float2*)(wp + 0));
                w01[t] = 0;
                w23[t] = pack2(b.x, b.y);
            } else if (hiEdge) {
                float2 a = __ldcs((const float2*)(wp + (WDIM - 2)));
                w01[t] = pack2(a.x, a.y);
                w23[t] = 0;
            } else {
                w01[t] = 0;
                w23[t] = 0;
            }
        }
    }

    float* pon = out + (size_t)n * CDIM * PLANE + (size_t)h * WDIM;

#pragma unroll 1
    for (int p = 0; p < NPAIR; p++) {
        const int s = p & (STAGES - 1);
        const uint32_t parity = (p >> 2) & 1;

        mbar_wait(smem_u32(&mbar[s]), parity);   // pair p data landed

#pragma unroll
        for (int half = 0; half < 2; half++) {
            // window (w0-2 .. w0+5) = staged offsets 4tx+4 .. 4tx+11:
            // exactly two aligned LDS.128 per tap row, conflict-free.
            const float* basep = &ring[s][half][ty * SPITCH + 4 * tx + 4];
            u64 acc01 = 0, acc23 = 0;
#pragma unroll
            for (int i = 0; i < 5; i++) {
                const float* rp = basep + i * SPITCH;
                float4 Q1 = *(const float4*)(rp);       // d0..d3
                float4 Q2 = *(const float4*)(rp + 4);   // d4..d7

                u64 p01 = pack2(Q1.x, Q1.y);
                u64 p12 = pack2(Q1.y, Q1.z);
                u64 p23 = pack2(Q1.z, Q1.w);
                u64 p34 = pack2(Q1.w, Q2.x);
                u64 p45 = pack2(Q2.x, Q2.y);
                u64 p56 = pack2(Q2.y, Q2.z);
                u64 p67 = pack2(Q2.z, Q2.w);

                const u64* wr01 = &w01[5 * i];
                const u64* wr23 = &w23[5 * i];
                fma2(acc01, p01, wr01[0]);
                fma2(acc23, p23, wr23[0]);
                fma2(acc01, p12, wr01[1]);
                fma2(acc23, p34, wr23[1]);
                fma2(acc01, p23, wr01[2]);
                fma2(acc23, p45, wr23[2]);
                fma2(acc01, p34, wr01[3]);
                fma2(acc23, p56, wr23[3]);
                fma2(acc01, p45, wr01[4]);
                fma2(acc23, p67, wr23[4]);
            }
            float o0, o1, o2, o3;
            unpack2(acc01, o0, o1);
            unpack2(acc23, o2, o3);
            float* pc = pon + (size_t)(2 * p + half) * PLANE;
            if (fullq) {
                __stcs((float2*)(pc + w0),     make_float2(o0, o1));
                __stcs((float2*)(pc + w0 + 2), make_float2(o2, o3));
            } else if (loEdge) {
                __stcs((float2*)(pc + 0), make_float2(o2, o3));
            } else if (hiEdge) {
                __stcs((float2*)(pc + (WDIM - 2)), make_float2(o0, o1));
            }
        }

        __syncthreads();                 // all reads of stage s done
        if (tid == 0 && p + 3 < NPAIR)
            issue(p + 3);                // reuse the stage freed at p-1
    }
}

extern "C" void kernel_launch(void* const* d_in, const int* in_sizes, int n_in,
                              void* d_out, int out_size) {
    const float* in1 = (const float*)d_in[0];
    const float* in2 = (const float*)d_in[1];
    float* out = (float*)d_out;

    // Build the 3D tensormap for in1 viewed as [W=768, H=384, N*C=128],
    // box [72, 12, 1]. Driver entry point fetched via the runtime so no
    // -lcuda link is needed. Host-only, deterministic, no allocation.
    typedef CUresult (*EncodeFn)(
        CUtensorMap*, CUtensorMapDataType, cuuint32_t, void*,
        const cuuint64_t*, const cuuint64_t*, const cuuint32_t*,
        const cuuint32_t*, CUtensorMapInterleave, CUtensorMapSwizzle,
        CUtensorMapL2promotion, CUtensorMapFloatOOBfill);
    void* fn = nullptr;
    cudaDriverEntryPointQueryResult qr;
    cudaGetDriverEntryPointByVersion("cuTensorMapEncodeTiled", &fn, 12000,
                                     cudaEnableDefault, &qr);
    CUtensorMap tmap;
    cuuint64_t dims[3]    = {WDIM, HDIM, (cuuint64_t)(NDIM * CDIM)};
    cuuint64_t strides[2] = {(cuuint64_t)WDIM * 4, (cuuint64_t)PLANE * 4};
    cuuint32_t box[3]     = {SPITCH, SROWS, 1};
    cuuint32_t estr[3]    = {1, 1, 1};
    ((EncodeFn)fn)(&tmap, CU_TENSOR_MAP_DATA_TYPE_FLOAT32, 3, (void*)in1,
                   dims, strides, box, estr,
                   CU_TENSOR_MAP_INTERLEAVE_NONE, CU_TENSOR_MAP_SWIZZLE_NONE,
                   CU_TENSOR_MAP_L2_PROMOTION_L2_128B,
                   CU_TENSOR_MAP_FLOAT_OOB_FILL_NONE);

    dim3 block(BX, BY);
    dim3 grid(GRIDX, HDIM / TILE_H, NDIM);  // 13 x 48 x 4
    lga_kernel<<<grid, block>>>(tmap, in2, out);
}